// round 10
// baseline (speedup 1.0000x reference)
#include <cuda_runtime.h>
#include <cstdint>

#define TPB    256
#define NBLK   444          // 3 per SM, single wave, persistent grid-stride
#define TROWS  256          // rows per tile
#define TF4    1024         // float4 per tile (16 KB)

// ---------------------------------------------------------------------------
// BinaryTreeRNN: out[i] = tree_combine( x[i,0:16] @ W_leaf^T + b_leaf )
// SINGLE kernel node. Persistent CTAs, cp.async.bulk (TMA bulk) double-buffer:
// tile j+1 streams global->smem via the async engine while warps compute tile
// j. W/bias/nodes live in shared (loaded/folded once per block); x rows are
// read with a rotated-chunk pattern that is 4-way-conflict optimal on the
// unswizzled TMA layout and keeps the matching W reads bank-disjoint.
// ---------------------------------------------------------------------------

// ---- packed fp32x2 helpers (sm_103a) --------------------------------------

__device__ __forceinline__ unsigned long long fma2(unsigned long long a,
                                                   unsigned long long b,
                                                   unsigned long long c)
{
    unsigned long long d;
    asm("fma.rn.f32x2 %0, %1, %2, %3;" : "=l"(d) : "l"(a), "l"(b), "l"(c));
    return d;
}

__device__ __forceinline__ unsigned long long pack2(float lo, float hi)
{
    unsigned long long d;
    asm("mov.b64 %0, {%1, %2};" : "=l"(d) : "f"(lo), "f"(hi));
    return d;
}

__device__ __forceinline__ void unpack2(unsigned long long v, float& lo, float& hi)
{
    asm("mov.b64 {%0, %1}, %2;" : "=f"(lo), "=f"(hi) : "l"(v));
}

// ---- mbarrier + bulk-async helpers -----------------------------------------

__device__ __forceinline__ void mbar_init(uint32_t a, uint32_t cnt)
{
    asm volatile("mbarrier.init.shared.b64 [%0], %1;" :: "r"(a), "r"(cnt) : "memory");
}

__device__ __forceinline__ void mbar_expect_tx(uint32_t a, uint32_t bytes)
{
    asm volatile("mbarrier.arrive.expect_tx.shared.b64 _, [%0], %1;"
                 :: "r"(a), "r"(bytes) : "memory");
}

__device__ __forceinline__ void mbar_arrive(uint32_t a)
{
    asm volatile("mbarrier.arrive.shared.b64 _, [%0];" :: "r"(a) : "memory");
}

__device__ __forceinline__ void mbar_wait(uint32_t a, uint32_t phase)
{
    asm volatile(
        "{\n\t"
        ".reg .pred P;\n\t"
        "LAB_WAIT_%=:\n\t"
        "mbarrier.try_wait.parity.acquire.cta.shared::cta.b64 P, [%0], %1, 0x989680;\n\t"
        "@P bra LAB_DONE_%=;\n\t"
        "bra LAB_WAIT_%=;\n\t"
        "LAB_DONE_%=:\n\t"
        "}"
        :: "r"(a), "r"(phase) : "memory");
}

__device__ __forceinline__ void bulk_g2s(uint32_t dst, const void* src,
                                         uint32_t bytes, uint32_t mbar)
{
    asm volatile(
        "cp.async.bulk.shared::cluster.global.mbarrier::complete_tx::bytes "
        "[%0], [%1], %2, [%3];"
        :: "r"(dst), "l"(src), "r"(bytes), "r"(mbar) : "memory");
}

// ---- main kernel -----------------------------------------------------------

__global__ void __launch_bounds__(TPB)
tree_rnn_kernel(const float4* __restrict__ x4, float* __restrict__ out, int n,
                const float* __restrict__ Wl,
                const float* __restrict__ bl,
                const float* __restrict__ w0,
                const float* __restrict__ w1,
                const float* __restrict__ w2,
                const float* __restrict__ b0,
                const float* __restrict__ b1,
                const float* __restrict__ b2,
                const float* __restrict__ om0,
                const float* __restrict__ om1,
                const float* __restrict__ om2)
{
    __shared__ __align__(16) float4 buf[2][TF4];       // 2 x 16 KB tile stages
    __shared__ __align__(16) float  sW[128];           // W_leaf raw [8][16]
    __shared__ float4 snode[7];                        // (A,M,C,b) per node
    __shared__ float4 sbias[2];                        // b_leaf
    __shared__ __align__(8) unsigned long long mbar[4];// full0,full1,empty0,empty1

    const int t = threadIdx.x;
    const int G = gridDim.x;
    const int ntiles = (n + TROWS - 1) / TROWS;

    // ---- once-per-block setup ----------------------------------------------
    if (t == 0) {
        mbar_init((uint32_t)__cvta_generic_to_shared(&mbar[0]), 1);    // full0
        mbar_init((uint32_t)__cvta_generic_to_shared(&mbar[1]), 1);    // full1
        mbar_init((uint32_t)__cvta_generic_to_shared(&mbar[2]), TPB);  // empty0
        mbar_init((uint32_t)__cvta_generic_to_shared(&mbar[3]), TPB);  // empty1
    }
    if (t < 7) {
        // fold softmax+w into per-node (A, M, C, b)   (fast-math, tiny)
        int i = t;   // 0-3: level2, 4-5: level1, 6: level0
        const float* om;
        float w, b;
        if (i < 4)      { om = om2 + 4 * i;       w = w2[i];     b = b2[i]; }
        else if (i < 6) { om = om1 + 4 * (i - 4); w = w1[i - 4]; b = b1[i - 4]; }
        else            { om = om0;               w = w0[0];     b = b0[0]; }
        float e0 = __expf(om[0]);
        float e1 = __expf(om[1]);
        float e2 = __expf(om[2]);
        float e3 = __expf(om[3]);
        float inv = __fdividef(w, e0 + e1 + e2 + e3);
        snode[i] = make_float4((e0 + e3) * inv, e1 * inv, e2 * inv, b);
    } else if (t >= 32 && t < 64) {
        reinterpret_cast<float4*>(sW)[t - 32] =
            reinterpret_cast<const float4*>(Wl)[t - 32];
    } else if (t == 64 || t == 65) {
        sbias[t - 64] = reinterpret_cast<const float4*>(bl)[t - 64];
    }
    __syncthreads();

    const uint32_t full0  = (uint32_t)__cvta_generic_to_shared(&mbar[0]);
    const uint32_t full1  = (uint32_t)__cvta_generic_to_shared(&mbar[1]);
    const uint32_t empty0 = (uint32_t)__cvta_generic_to_shared(&mbar[2]);
    const uint32_t empty1 = (uint32_t)__cvta_generic_to_shared(&mbar[3]);
    const uint32_t bufa0  = (uint32_t)__cvta_generic_to_shared(&buf[0][0]);
    const uint32_t bufa1  = (uint32_t)__cvta_generic_to_shared(&buf[1][0]);

    // ---- prologue: fill both stages ----------------------------------------
    if (t == 0) {
        int t0i = blockIdx.x;
        if (t0i < ntiles) {
            int rows = n - t0i * TROWS; if (rows > TROWS) rows = TROWS;
            mbar_expect_tx(full0, (uint32_t)(rows * 64));
            bulk_g2s(bufa0, x4 + (size_t)t0i * TF4, (uint32_t)(rows * 64), full0);
        }
        int t1i = t0i + G;
        if (t1i < ntiles) {
            int rows = n - t1i * TROWS; if (rows > TROWS) rows = TROWS;
            mbar_expect_tx(full1, (uint32_t)(rows * 64));
            bulk_g2s(bufa1, x4 + (size_t)t1i * TF4, (uint32_t)(rows * 64), full1);
        }
    }

    const int rot = (t >> 1) & 3;

    float4 b0v = sbias[0];
    float4 b1v = sbias[1];
    const float bb[8] = { b0v.x, b0v.y, b0v.z, b0v.w,
                          b1v.x, b1v.y, b1v.z, b1v.w };

    // per-round compute body
    auto compute_tile = [&](const float4* bufp, int tile) {
        int row = tile * TROWS + t;
        if (row >= n) return;
        const float4* brow = bufp + (t << 2);

        unsigned long long acc[8];
#pragma unroll
        for (int j = 0; j < 8; j++) acc[j] = 0ULL;

#pragma unroll
        for (int c = 0; c < 4; c++) {
            int p = (c + rot) & 3;           // rotated chunk: 4-way optimal banks
            float4 xv = brow[p];             // LDS.128 (unswizzled TMA layout)
            unsigned long long xlo = pack2(xv.x, xv.y);
            unsigned long long xhi = pack2(xv.z, xv.w);
#pragma unroll
            for (int j = 0; j < 8; j++) {
                // matching W chunk p: 4 distinct addrs, bank-disjoint -> 1 wf
                ulonglong2 wq =
                    *reinterpret_cast<const ulonglong2*>(&sW[j * 16 + p * 4]);
                acc[j] = fma2(wq.x, xlo, acc[j]);
                acc[j] = fma2(wq.y, xhi, acc[j]);
            }
        }

        float h[8];
#pragma unroll
        for (int j = 0; j < 8; j++) {
            float lo, hi;
            unpack2(acc[j], lo, hi);
            h[j] = lo + hi + bb[j];
        }

        float g[4];
#pragma unroll
        for (int k = 0; k < 4; k++) {
            float4 np = snode[k];
            float l = h[2 * k], r = h[2 * k + 1];
            float s = l + r;
            g[k] = fmaf(np.x, s, fmaf(np.y, l * r, fmaf(np.z, __sinf(s), np.w)));
        }
        float u[2];
#pragma unroll
        for (int k = 0; k < 2; k++) {
            float4 np = snode[4 + k];
            float l = g[2 * k], r = g[2 * k + 1];
            float s = l + r;
            u[k] = fmaf(np.x, s, fmaf(np.y, l * r, fmaf(np.z, __sinf(s), np.w)));
        }
        {
            float4 np = snode[6];
            float l = u[0], r = u[1];
            float s = l + r;
            out[row] = fmaf(np.x, s, fmaf(np.y, l * r, fmaf(np.z, __sinf(s), np.w)));
        }
    };

    // producer refill for stage (by thread 0 only)
    auto refill = [&](uint32_t emptyb, uint32_t fullb, uint32_t bufa,
                      int nt, int& ep) {
        if (nt < ntiles) {
            mbar_wait(emptyb, (uint32_t)ep);   // all 256 consumers done
            ep ^= 1;
            int rows = n - nt * TROWS; if (rows > TROWS) rows = TROWS;
            mbar_expect_tx(fullb, (uint32_t)(rows * 64));
            bulk_g2s(bufa, x4 + (size_t)nt * TF4, (uint32_t)(rows * 64), fullb);
        }
    };

    // ---- main double-buffered loop -----------------------------------------
    int fp0 = 0, fp1 = 0, ep0 = 0, ep1 = 0;
    int tile = blockIdx.x;
    while (tile < ntiles) {
        // stage 0
        mbar_wait(full0, (uint32_t)fp0); fp0 ^= 1;
        compute_tile(buf[0], tile);
        mbar_arrive(empty0);
        if (t == 0) refill(empty0, full0, bufa0, tile + 2 * G, ep0);
        tile += G;
        if (tile >= ntiles) break;

        // stage 1
        mbar_wait(full1, (uint32_t)fp1); fp1 ^= 1;
        compute_tile(buf[1], tile);
        mbar_arrive(empty1);
        if (t == 0) refill(empty1, full1, bufa1, tile + 2 * G, ep1);
        tile += G;
    }
}

extern "C" void kernel_launch(void* const* d_in, const int* in_sizes, int n_in,
                              void* d_out, int out_size)
{
    const float* x      = (const float*)d_in[0];
    const float* W_leaf = (const float*)d_in[1];
    const float* b_leaf = (const float*)d_in[2];
    const float* w0     = (const float*)d_in[3];
    const float* w1     = (const float*)d_in[4];
    const float* w2     = (const float*)d_in[5];
    const float* b0     = (const float*)d_in[6];
    const float* b1     = (const float*)d_in[7];
    const float* b2     = (const float*)d_in[8];
    const float* om0    = (const float*)d_in[9];
    const float* om1    = (const float*)d_in[10];
    const float* om2    = (const float*)d_in[11];

    int n = in_sizes[0] / 16;
    int ntiles = (n + TROWS - 1) / TROWS;
    int blocks = NBLK;
    if (blocks > ntiles) blocks = ntiles;
    if (blocks < 1) blocks = 1;

    tree_rnn_kernel<<<blocks, TPB>>>(
        reinterpret_cast<const float4*>(x), (float*)d_out, n,
        W_leaf, b_leaf, w0, w1, w2, b0, b1, b2, om0, om1, om2);
}

// round 11
// speedup vs baseline: 1.2418x; 1.2418x over previous
#include <cuda_runtime.h>
#include <cstdint>

#define TPB  128              // 128 threads, 128 rows per block (8 KB tile)

// ---------------------------------------------------------------------------
// BinaryTreeRNN: out[i] = tree_combine( x[i,0:16] @ W_leaf^T + b_leaf )
// 2-node graph:
//   (1) D2D memcpy of raw W_leaf into __constant__ (even/odd accumulator
//       packing needs no interleave -> no setup kernel).
//   (2) main kernel, 128-thread blocks: finer barrier granularity (16 groups
//       per SM) keeps DRAM loads in flight through other groups' compute.
//       Per-block softmax fold is fast-math and hidden under the tile LDGs;
//       bias is folded into the packed accumulator init via uniform __ldg.
// ---------------------------------------------------------------------------

__constant__ __align__(16) float cW[128];   // W_leaf, raw row-major [8][16]

// ---- packed fp32x2 helpers (sm_103a) --------------------------------------

__device__ __forceinline__ unsigned long long fma2(unsigned long long a,
                                                   unsigned long long b,
                                                   unsigned long long c)
{
    unsigned long long d;
    asm("fma.rn.f32x2 %0, %1, %2, %3;" : "=l"(d) : "l"(a), "l"(b), "l"(c));
    return d;
}

__device__ __forceinline__ unsigned long long pack2(float lo, float hi)
{
    unsigned long long d;
    asm("mov.b64 %0, {%1, %2};" : "=l"(d) : "f"(lo), "f"(hi));
    return d;
}

__device__ __forceinline__ void unpack2(unsigned long long v, float& lo, float& hi)
{
    asm("mov.b64 {%0, %1}, %2;" : "=f"(lo), "=f"(hi) : "l"(v));
}

// ---- main kernel -----------------------------------------------------------

__global__ void __launch_bounds__(TPB)
tree_rnn_kernel(const float4* __restrict__ x4, float* __restrict__ out, int n,
                const float* __restrict__ bl,
                const float* __restrict__ w0,
                const float* __restrict__ w1,
                const float* __restrict__ w2,
                const float* __restrict__ b0,
                const float* __restrict__ b1,
                const float* __restrict__ b2,
                const float* __restrict__ om0,
                const float* __restrict__ om1,
                const float* __restrict__ om2)
{
    __shared__ float4 tile[TPB * 4];   // 128 rows x 16 floats, XOR-swizzled
    __shared__ float4 snode[7];        // (A, M, C, b) per tree node

    const int t = threadIdx.x;

    // ---- Phase B FIRST: coalesced tile load, XOR-swizzled store -----------
    const int n4 = n * 4;
    const int base4 = blockIdx.x * (TPB * 4);
#pragma unroll
    for (int j = 0; j < 4; j++) {
        int li = j * TPB + t;
        int g4 = base4 + li;
        float4 v;
        if (g4 < n4) v = x4[g4];
        else         v = make_float4(0.f, 0.f, 0.f, 0.f);
        int r = li >> 2;
        int q = li & 3;
        tile[(r << 2) + (q ^ ((r >> 1) & 3))] = v;
    }

    // ---- bias: uniform L2-hot loads, in flight under the tile LDGs --------
    float4 bv0 = __ldg(reinterpret_cast<const float4*>(bl));
    float4 bv1 = __ldg(reinterpret_cast<const float4*>(bl) + 1);
    const float bj[8] = { bv0.x, bv0.y, bv0.z, bv0.w,
                          bv1.x, bv1.y, bv1.z, bv1.w };

    // ---- Phase A: fold softmax+w into (A,M,C,b), hidden under Phase B -----
    if (t < 7) {
        int i = t;   // 0-3: level2, 4-5: level1, 6: level0
        const float* om;
        float w, b;
        if (i < 4)      { om = om2 + 4 * i;       w = w2[i];     b = b2[i]; }
        else if (i < 6) { om = om1 + 4 * (i - 4); w = w1[i - 4]; b = b1[i - 4]; }
        else            { om = om0;               w = w0[0];     b = b0[0]; }
        float e0 = __expf(om[0]);
        float e1 = __expf(om[1]);
        float e2 = __expf(om[2]);
        float e3 = __expf(om[3]);
        float inv = __fdividef(w, e0 + e1 + e2 + e3);   // fold w into coeffs
        snode[i] = make_float4((e0 + e3) * inv, e1 * inv, e2 * inv, b);
    }
    __syncthreads();

    const int row = blockIdx.x * TPB + t;
    if (row >= n) return;

    // gather own row as x-pairs: float4 slot == ulonglong2{(x0,x1),(x2,x3)}
    const ulonglong2* tb = reinterpret_cast<const ulonglong2*>(tile);
    const int swz = (t >> 1) & 3;
    ulonglong2 xq0 = tb[(t << 2) + (0 ^ swz)];
    ulonglong2 xq1 = tb[(t << 2) + (1 ^ swz)];
    ulonglong2 xq2 = tb[(t << 2) + (2 ^ swz)];
    ulonglong2 xq3 = tb[(t << 2) + (3 ^ swz)];

    // leaf matvec: acc_j = ((even-k partial)+b_j, (odd-k partial)), W from
    // the constant port in natural layout (cw[j*4+c] = W[j][4c..4c+3]).
    const ulonglong2* cw = reinterpret_cast<const ulonglong2*>(cW);
    float h[8];
#pragma unroll
    for (int j = 0; j < 8; j++) {
        unsigned long long acc = pack2(bj[j], 0.0f);   // bias folded into init
        ulonglong2 w0q = cw[j * 4 + 0];
        acc = fma2(w0q.x, xq0.x, acc);
        acc = fma2(w0q.y, xq0.y, acc);
        ulonglong2 w1q = cw[j * 4 + 1];
        acc = fma2(w1q.x, xq1.x, acc);
        acc = fma2(w1q.y, xq1.y, acc);
        ulonglong2 w2q = cw[j * 4 + 2];
        acc = fma2(w2q.x, xq2.x, acc);
        acc = fma2(w2q.y, xq2.y, acc);
        ulonglong2 w3q = cw[j * 4 + 3];
        acc = fma2(w3q.x, xq3.x, acc);
        acc = fma2(w3q.y, xq3.y, acc);
        float lo, hi;
        unpack2(acc, lo, hi);
        h[j] = lo + hi;
    }

    // tree combine: val = A*s + M*(l*r) + C*sin(s) + b
    float g[4];
#pragma unroll
    for (int k = 0; k < 4; k++) {
        float4 np = snode[k];
        float l = h[2 * k], r = h[2 * k + 1];
        float s = l + r;
        g[k] = fmaf(np.x, s, fmaf(np.y, l * r, fmaf(np.z, __sinf(s), np.w)));
    }
    float u[2];
#pragma unroll
    for (int k = 0; k < 2; k++) {
        float4 np = snode[4 + k];
        float l = g[2 * k], r = g[2 * k + 1];
        float s = l + r;
        u[k] = fmaf(np.x, s, fmaf(np.y, l * r, fmaf(np.z, __sinf(s), np.w)));
    }
    {
        float4 np = snode[6];
        float l = u[0], r = u[1];
        float s = l + r;
        out[row] = fmaf(np.x, s, fmaf(np.y, l * r, fmaf(np.z, __sinf(s), np.w)));
    }
}

extern "C" void kernel_launch(void* const* d_in, const int* in_sizes, int n_in,
                              void* d_out, int out_size)
{
    const float* x      = (const float*)d_in[0];
    const float* W_leaf = (const float*)d_in[1];
    const float* b_leaf = (const float*)d_in[2];
    const float* w0     = (const float*)d_in[3];
    const float* w1     = (const float*)d_in[4];
    const float* w2     = (const float*)d_in[5];
    const float* b0     = (const float*)d_in[6];
    const float* b1     = (const float*)d_in[7];
    const float* b2     = (const float*)d_in[8];
    const float* om0    = (const float*)d_in[9];
    const float* om1    = (const float*)d_in[10];
    const float* om2    = (const float*)d_in[11];

    int n = in_sizes[0] / 16;

    // single D2D memcpy node: raw W_leaf straight into constant memory
    cudaMemcpyToSymbolAsync(cW, W_leaf, 128 * sizeof(float), 0,
                            cudaMemcpyDeviceToDevice);

    int blocks = (n + TPB - 1) / TPB;
    tree_rnn_kernel<<<blocks, TPB>>>(
        reinterpret_cast<const float4*>(x), (float*)d_out, n,
        b_leaf, w0, w1, w2, b0, b1, b2, om0, om1, om2);
}

// round 12
// speedup vs baseline: 1.2895x; 1.0384x over previous
#include <cuda_runtime.h>
#include <cstdint>

#define TPB  256

// ---------------------------------------------------------------------------
// BinaryTreeRNN: out[i] = tree_combine( x[i,0:16] @ W_leaf^T + b_leaf )
// 2-node graph:
//   (1) D2D memcpy of raw W_leaf into __constant__ (even/odd accumulator
//       packing needs no interleave -> no setup kernel).
//   (2) main kernel, 256-thread blocks, reg-capped for occupancy: softmax
//       fold hidden under the tile LDGs; bias folded into the packed
//       accumulator init via uniform __ldg (no extra FADDs, no bias LDS).
// ---------------------------------------------------------------------------

__constant__ __align__(16) float cW[128];   // W_leaf, raw row-major [8][16]

// ---- packed fp32x2 helpers (sm_103a) --------------------------------------

__device__ __forceinline__ unsigned long long fma2(unsigned long long a,
                                                   unsigned long long b,
                                                   unsigned long long c)
{
    unsigned long long d;
    asm("fma.rn.f32x2 %0, %1, %2, %3;" : "=l"(d) : "l"(a), "l"(b), "l"(c));
    return d;
}

__device__ __forceinline__ unsigned long long pack2(float lo, float hi)
{
    unsigned long long d;
    asm("mov.b64 %0, {%1, %2};" : "=l"(d) : "f"(lo), "f"(hi));
    return d;
}

__device__ __forceinline__ void unpack2(unsigned long long v, float& lo, float& hi)
{
    asm("mov.b64 {%0, %1}, %2;" : "=f"(lo), "=f"(hi) : "l"(v));
}

// ---- main kernel -----------------------------------------------------------

__global__ void __launch_bounds__(TPB, 7)
tree_rnn_kernel(const float4* __restrict__ x4, float* __restrict__ out, int n,
                const float* __restrict__ bl,
                const float* __restrict__ w0,
                const float* __restrict__ w1,
                const float* __restrict__ w2,
                const float* __restrict__ b0,
                const float* __restrict__ b1,
                const float* __restrict__ b2,
                const float* __restrict__ om0,
                const float* __restrict__ om1,
                const float* __restrict__ om2)
{
    __shared__ float4 tile[TPB * 4];   // 256 rows x 16 floats, XOR-swizzled
    __shared__ float4 snode[7];        // (A, M, C, b) per tree node

    const int t = threadIdx.x;

    // ---- Phase B FIRST: coalesced tile load, XOR-swizzled store -----------
    const int n4 = n * 4;
    const int base4 = blockIdx.x * (TPB * 4);
#pragma unroll
    for (int j = 0; j < 4; j++) {
        int li = j * TPB + t;
        int g4 = base4 + li;
        float4 v;
        if (g4 < n4) v = x4[g4];
        else         v = make_float4(0.f, 0.f, 0.f, 0.f);
        int r = li >> 2;
        int q = li & 3;
        tile[(r << 2) + (q ^ ((r >> 1) & 3))] = v;
    }

    // ---- bias: uniform L2-hot loads, in flight alongside the tile LDGs ----
    float4 bv0 = __ldg(reinterpret_cast<const float4*>(bl));
    float4 bv1 = __ldg(reinterpret_cast<const float4*>(bl) + 1);
    const float bj[8] = { bv0.x, bv0.y, bv0.z, bv0.w,
                          bv1.x, bv1.y, bv1.z, bv1.w };

    // ---- Phase A: fold softmax+w into (A,M,C,b), hidden under Phase B -----
    if (t < 7) {
        int i = t;   // 0-3: level2, 4-5: level1, 6: level0
        const float* om;
        float w, b;
        if (i < 4)      { om = om2 + 4 * i;       w = w2[i];     b = b2[i]; }
        else if (i < 6) { om = om1 + 4 * (i - 4); w = w1[i - 4]; b = b1[i - 4]; }
        else            { om = om0;               w = w0[0];     b = b0[0]; }
        float e0 = __expf(om[0]);
        float e1 = __expf(om[1]);
        float e2 = __expf(om[2]);
        float e3 = __expf(om[3]);
        float inv = __fdividef(w, e0 + e1 + e2 + e3);   // fold w into coeffs
        snode[i] = make_float4((e0 + e3) * inv, e1 * inv, e2 * inv, b);
    }
    __syncthreads();

    const int row = blockIdx.x * TPB + t;
    if (row >= n) return;

    // gather own row as x-pairs: float4 slot == ulonglong2{(x0,x1),(x2,x3)}
    const ulonglong2* tb = reinterpret_cast<const ulonglong2*>(tile);
    const int swz = (t >> 1) & 3;
    ulonglong2 xq0 = tb[(t << 2) + (0 ^ swz)];
    ulonglong2 xq1 = tb[(t << 2) + (1 ^ swz)];
    ulonglong2 xq2 = tb[(t << 2) + (2 ^ swz)];
    ulonglong2 xq3 = tb[(t << 2) + (3 ^ swz)];

    // leaf matvec: acc_j = ((even-k partial)+b_j, (odd-k partial)), W from
    // the constant port in natural layout (cw[j*4+c] = W[j][4c..4c+3]).
    const ulonglong2* cw = reinterpret_cast<const ulonglong2*>(cW);
    float h[8];
#pragma unroll
    for (int j = 0; j < 8; j++) {
        unsigned long long acc = pack2(bj[j], 0.0f);   // bias folded into init
        ulonglong2 w0q = cw[j * 4 + 0];
        acc = fma2(w0q.x, xq0.x, acc);
        acc = fma2(w0q.y, xq0.y, acc);
        ulonglong2 w1q = cw[j * 4 + 1];
        acc = fma2(w1q.x, xq1.x, acc);
        acc = fma2(w1q.y, xq1.y, acc);
        ulonglong2 w2q = cw[j * 4 + 2];
        acc = fma2(w2q.x, xq2.x, acc);
        acc = fma2(w2q.y, xq2.y, acc);
        ulonglong2 w3q = cw[j * 4 + 3];
        acc = fma2(w3q.x, xq3.x, acc);
        acc = fma2(w3q.y, xq3.y, acc);
        float lo, hi;
        unpack2(acc, lo, hi);
        h[j] = lo + hi;
    }

    // tree combine: val = A*s + M*(l*r) + C*sin(s) + b
    float g[4];
#pragma unroll
    for (int k = 0; k < 4; k++) {
        float4 np = snode[k];
        float l = h[2 * k], r = h[2 * k + 1];
        float s = l + r;
        g[k] = fmaf(np.x, s, fmaf(np.y, l * r, fmaf(np.z, __sinf(s), np.w)));
    }
    float u[2];
#pragma unroll
    for (int k = 0; k < 2; k++) {
        float4 np = snode[4 + k];
        float l = g[2 * k], r = g[2 * k + 1];
        float s = l + r;
        u[k] = fmaf(np.x, s, fmaf(np.y, l * r, fmaf(np.z, __sinf(s), np.w)));
    }
    {
        float4 np = snode[6];
        float l = u[0], r = u[1];
        float s = l + r;
        out[row] = fmaf(np.x, s, fmaf(np.y, l * r, fmaf(np.z, __sinf(s), np.w)));
    }
}

extern "C" void kernel_launch(void* const* d_in, const int* in_sizes, int n_in,
                              void* d_out, int out_size)
{
    const float* x      = (const float*)d_in[0];
    const float* W_leaf = (const float*)d_in[1];
    const float* b_leaf = (const float*)d_in[2];
    const float* w0     = (const float*)d_in[3];
    const float* w1     = (const float*)d_in[4];
    const float* w2     = (const float*)d_in[5];
    const float* b0     = (const float*)d_in[6];
    const float* b1     = (const float*)d_in[7];
    const float* b2     = (const float*)d_in[8];
    const float* om0    = (const float*)d_in[9];
    const float* om1    = (const float*)d_in[10];
    const float* om2    = (const float*)d_in[11];

    int n = in_sizes[0] / 16;

    // single D2D memcpy node: raw W_leaf straight into constant memory
    cudaMemcpyToSymbolAsync(cW, W_leaf, 128 * sizeof(float), 0,
                            cudaMemcpyDeviceToDevice);

    int blocks = (n + TPB - 1) / TPB;
    tree_rnn_kernel<<<blocks, TPB>>>(
        reinterpret_cast<const float4*>(x), (float*)d_out, n,
        b_leaf, w0, w1, w2, b0, b1, b2, om0, om1, om2);
}